// round 1
// baseline (speedup 1.0000x reference)
#include <cuda_runtime.h>
#include <mma.h>
#include <math.h>

using namespace nvcuda;

#define N_NODES_C 20000
#define N_EDGES_C 320000
#define NH 128
#define DIN 262
#define NLAYERS 3
#define BN_EPS 1e-5f

// ---------------- scratch (static __device__ allocations are allowed) ----------------
__device__ float g_x[N_NODES_C * NH];            // working node features (10.24 MB)
__device__ float g_h1[(size_t)N_EDGES_C * NH];   // hpre (163.84 MB)
__device__ float g_norm[N_EDGES_C];
__device__ float g_dot[N_EDGES_C];
__device__ float g_stats[2 * NH];                // col sums / sumsq
__device__ float g_bnA[NH];                      // scale
__device__ float g_bnB[NH];                      // shift
__device__ float g_agg[N_NODES_C * NH];          // segment-sum accumulator

__device__ __forceinline__ float psi_f(float z) {
    return copysignf(log1pf(fabsf(z)), z);
}
__device__ __forceinline__ float sigmoid_f(float z) {
    return 1.0f / (1.0f + expf(-z));
}

// ---------------- per-edge Minkowski norms/dots (warp per edge; x is L2-resident) ----
__global__ void k_prep(const int* __restrict__ ei) {
    int e = blockIdx.x * 8 + (threadIdx.x >> 5);
    if (e >= N_EDGES_C) return;
    int lane = threadIdx.x & 31;
    int r = ei[e];
    int c = ei[N_EDGES_C + e];
    const float* xi = g_x + (size_t)r * NH;
    const float* xj = g_x + (size_t)c * NH;
    float dd = 0.f, ij = 0.f;
#pragma unroll
    for (int t = 0; t < 4; t++) {
        int k = lane + 32 * t;
        float a = xi[k], b = xj[k];
        float d = a - b;
        float sgn = (k == 0) ? 1.f : -1.f;
        dd = fmaf(sgn * d, d, dd);
        ij = fmaf(sgn * a, b, ij);
    }
#pragma unroll
    for (int o = 16; o; o >>= 1) {
        dd += __shfl_xor_sync(0xffffffffu, dd, o);
        ij += __shfl_xor_sync(0xffffffffu, ij, o);
    }
    if (lane == 0) {
        g_norm[e] = psi_f(dd);
        g_dot[e]  = psi_f(ij);
    }
}

// ---------------- GEMM1: hpre = [x_i | x_j | ea | norm | dot] @ W1  (tf32 wmma) ------
// block = 128 threads (4 warps), tile = 32 edges x 128 cols, K padded 262 -> 272.
__global__ void k_gemm1(const int* __restrict__ ei, const float* __restrict__ ea,
                        const float* __restrict__ W1) {
    __shared__ float As[32][24];   // 32 edges x 16 k (pad 24)
    __shared__ float Bs[16][128];
    __shared__ int srow[32], scol[32];

    int tid = threadIdx.x;
    int warp = tid >> 5;
    int wy = warp >> 1, wx = warp & 1;
    int e0 = blockIdx.x * 32;

    if (tid < 32) { srow[tid] = ei[e0 + tid]; scol[tid] = ei[N_EDGES_C + e0 + tid]; }
    __syncthreads();

    wmma::fragment<wmma::accumulator, 16, 16, 8, float> acc[4];
#pragma unroll
    for (int j = 0; j < 4; j++) wmma::fill_fragment(acc[j], 0.f);

    for (int kc = 0; kc < 272; kc += 16) {
        // gather A chunk
#pragma unroll
        for (int i = 0; i < 4; i++) {
            int idx = tid + 128 * i;          // 512 elems
            int e = idx >> 4, k = idx & 15;
            int kg = kc + k;
            float v;
            if (kg < 128)        v = g_x[(size_t)srow[e] * NH + kg];
            else if (kg < 256)   v = g_x[(size_t)scol[e] * NH + (kg - 128)];
            else if (kg < 260)   v = ea[(size_t)(e0 + e) * 4 + (kg - 256)];
            else if (kg == 260)  v = g_norm[e0 + e];
            else if (kg == 261)  v = g_dot[e0 + e];
            else                 v = 0.f;
            As[e][k] = v;
        }
        // load B chunk
#pragma unroll
        for (int i = 0; i < 16; i++) {
            int idx = tid + 128 * i;          // 2048 elems
            int k = idx >> 7, c = idx & 127;
            int kg = kc + k;
            Bs[k][c] = (kg < DIN) ? W1[(size_t)kg * NH + c] : 0.f;
        }
        __syncthreads();
#pragma unroll
        for (int kk = 0; kk < 16; kk += 8) {
            wmma::fragment<wmma::matrix_a, 16, 16, 8, wmma::precision::tf32, wmma::row_major> af;
            wmma::load_matrix_sync(af, &As[wy * 16][kk], 24);
#pragma unroll
            for (int t = 0; t < af.num_elements; t++) af.x[t] = wmma::__float_to_tf32(af.x[t]);
#pragma unroll
            for (int j = 0; j < 4; j++) {
                wmma::fragment<wmma::matrix_b, 16, 16, 8, wmma::precision::tf32, wmma::row_major> bf;
                wmma::load_matrix_sync(bf, &Bs[kk][wx * 64 + j * 16], 128);
#pragma unroll
                for (int t = 0; t < bf.num_elements; t++) bf.x[t] = wmma::__float_to_tf32(bf.x[t]);
                wmma::mma_sync(acc[j], af, bf, acc[j]);
            }
        }
        __syncthreads();
    }
#pragma unroll
    for (int j = 0; j < 4; j++)
        wmma::store_matrix_sync(&g_h1[(size_t)(e0 + wy * 16) * NH + wx * 64 + j * 16],
                                acc[j], NH, wmma::mem_row_major);
}

// ---------------- BN column stats over hpre -----------------------------------------
__global__ void k_stats() {
    int c = threadIdx.x;                 // 128 threads, one column each
    size_t base = (size_t)blockIdx.x * 512;
    float s = 0.f, q = 0.f;
    for (int r = 0; r < 512; r++) {
        float v = g_h1[(base + r) * NH + c];
        s += v;
        q = fmaf(v, v, q);
    }
    atomicAdd(&g_stats[c], s);
    atomicAdd(&g_stats[NH + c], q);
}

__global__ void k_bnfin(const float* __restrict__ gamma, const float* __restrict__ beta) {
    int c = threadIdx.x;
    float inv = 1.f / (float)N_EDGES_C;
    float mean = g_stats[c] * inv;
    float var = g_stats[NH + c] * inv - mean * mean;
    float sc = gamma[c] * rsqrtf(var + BN_EPS);
    g_bnA[c] = sc;
    g_bnB[c] = beta[c] - mean * sc;
}

// ---------------- fused: BN+ReLU -> W2 GEMM -> gate -> Wa GEMM -> Wb dot -> scatter --
__global__ void k_fused(const int* __restrict__ ei,
                        const float* __restrict__ W2, const float* __restrict__ b2,
                        const float* __restrict__ Wa, const float* __restrict__ ba,
                        const float* __restrict__ Wb,
                        const float* __restrict__ Wm, const float* __restrict__ bm) {
    __shared__ float S0[32][136];
    __shared__ float S1[32][136];
    __shared__ float Bs[16][128];
    __shared__ float s_sh[32];

    int tid = threadIdx.x;               // 128
    int warp = tid >> 5, lane = tid & 31;
    int wy = warp >> 1, wx = warp & 1;
    int e0 = blockIdx.x * 32;

    // phase 0: load hpre tile, apply BN + ReLU
#pragma unroll
    for (int i = 0; i < 32; i++) {
        int idx = tid + 128 * i;
        int e = idx >> 7, c = idx & 127;
        float v = g_h1[(size_t)(e0 + e) * NH + c];
        v = fmaf(v, g_bnA[c], g_bnB[c]);
        S0[e][c] = fmaxf(v, 0.f);
    }
    __syncthreads();

    wmma::fragment<wmma::accumulator, 16, 16, 8, float> acc[4];
#pragma unroll
    for (int j = 0; j < 4; j++) wmma::fill_fragment(acc[j], 0.f);

    // GEMM: pre_mij = S0 @ W2
    for (int kc = 0; kc < 128; kc += 16) {
#pragma unroll
        for (int i = 0; i < 16; i++) {
            int idx = tid + 128 * i;
            int k = idx >> 7, c = idx & 127;
            Bs[k][c] = W2[(size_t)(kc + k) * NH + c];
        }
        __syncthreads();
#pragma unroll
        for (int kk = 0; kk < 16; kk += 8) {
            wmma::fragment<wmma::matrix_a, 16, 16, 8, wmma::precision::tf32, wmma::row_major> af;
            wmma::load_matrix_sync(af, &S0[wy * 16][kc + kk], 136);
#pragma unroll
            for (int t = 0; t < af.num_elements; t++) af.x[t] = wmma::__float_to_tf32(af.x[t]);
#pragma unroll
            for (int j = 0; j < 4; j++) {
                wmma::fragment<wmma::matrix_b, 16, 16, 8, wmma::precision::tf32, wmma::row_major> bf;
                wmma::load_matrix_sync(bf, &Bs[kk][wx * 64 + j * 16], 128);
#pragma unroll
                for (int t = 0; t < bf.num_elements; t++) bf.x[t] = wmma::__float_to_tf32(bf.x[t]);
                wmma::mma_sync(acc[j], af, bf, acc[j]);
            }
        }
        __syncthreads();
    }
#pragma unroll
    for (int j = 0; j < 4; j++)
        wmma::store_matrix_sync(&S1[wy * 16][wx * 64 + j * 16], acc[j], 136, wmma::mem_row_major);
    __syncthreads();

    // bias + ReLU
#pragma unroll
    for (int i = 0; i < 32; i++) {
        int idx = tid + 128 * i;
        int e = idx >> 7, c = idx & 127;
        S1[e][c] = fmaxf(S1[e][c] + b2[c], 0.f);
    }
    __syncthreads();

    // sigmoid gate: warp handles 8 edges
    {
        float bmv = bm[0];
        for (int t = 0; t < 8; t++) {
            int e = warp * 8 + t;
            float p = 0.f;
#pragma unroll
            for (int u = 0; u < 4; u++) {
                int c = lane + 32 * u;
                p = fmaf(S1[e][c], Wm[c], p);
            }
#pragma unroll
            for (int o = 16; o; o >>= 1) p += __shfl_xor_sync(0xffffffffu, p, o);
            float wg = sigmoid_f(p + bmv);
#pragma unroll
            for (int u = 0; u < 4; u++) {
                int c = lane + 32 * u;
                S1[e][c] *= wg;
            }
        }
    }
    __syncthreads();

    // GEMM: pre_t = S1 @ Wa  -> S0 (reuse)
#pragma unroll
    for (int j = 0; j < 4; j++) wmma::fill_fragment(acc[j], 0.f);
    for (int kc = 0; kc < 128; kc += 16) {
#pragma unroll
        for (int i = 0; i < 16; i++) {
            int idx = tid + 128 * i;
            int k = idx >> 7, c = idx & 127;
            Bs[k][c] = Wa[(size_t)(kc + k) * NH + c];
        }
        __syncthreads();
#pragma unroll
        for (int kk = 0; kk < 16; kk += 8) {
            wmma::fragment<wmma::matrix_a, 16, 16, 8, wmma::precision::tf32, wmma::row_major> af;
            wmma::load_matrix_sync(af, &S1[wy * 16][kc + kk], 136);
#pragma unroll
            for (int t = 0; t < af.num_elements; t++) af.x[t] = wmma::__float_to_tf32(af.x[t]);
#pragma unroll
            for (int j = 0; j < 4; j++) {
                wmma::fragment<wmma::matrix_b, 16, 16, 8, wmma::precision::tf32, wmma::row_major> bf;
                wmma::load_matrix_sync(bf, &Bs[kk][wx * 64 + j * 16], 128);
#pragma unroll
                for (int t = 0; t < bf.num_elements; t++) bf.x[t] = wmma::__float_to_tf32(bf.x[t]);
                wmma::mma_sync(acc[j], af, bf, acc[j]);
            }
        }
        __syncthreads();
    }
#pragma unroll
    for (int j = 0; j < 4; j++)
        wmma::store_matrix_sync(&S0[wy * 16][wx * 64 + j * 16], acc[j], 136, wmma::mem_row_major);
    __syncthreads();

    // ReLU(t + ba)
#pragma unroll
    for (int i = 0; i < 32; i++) {
        int idx = tid + 128 * i;
        int e = idx >> 7, c = idx & 127;
        S0[e][c] = fmaxf(S0[e][c] + ba[c], 0.f);
    }
    __syncthreads();

    // s = t @ Wb (per-edge scalar)
    for (int t = 0; t < 8; t++) {
        int e = warp * 8 + t;
        float p = 0.f;
#pragma unroll
        for (int u = 0; u < 4; u++) {
            int c = lane + 32 * u;
            p = fmaf(S0[e][c], Wb[c], p);
        }
#pragma unroll
        for (int o = 16; o; o >>= 1) p += __shfl_xor_sync(0xffffffffu, p, o);
        if (lane == 0) s_sh[e] = p;
    }
    __syncthreads();

    // trans = clip(x_diff * s) ; segment-sum via atomics (x rows are L2-resident)
#pragma unroll
    for (int i = 0; i < 32; i++) {
        int idx = tid + 128 * i;
        int el = idx >> 7, k = idx & 127;
        int e = e0 + el;
        int r = ei[e];
        int c = ei[N_EDGES_C + e];
        float d = g_x[(size_t)r * NH + k] - g_x[(size_t)c * NH + k];
        float v = d * s_sh[el];
        v = fminf(fmaxf(v, -100.f), 100.f);
        atomicAdd(&g_agg[(size_t)r * NH + k], v);
    }
}

// ---------------- x += agg ----------------------------------------------------------
__global__ void k_apply() {
    int i = blockIdx.x * 256 + threadIdx.x;
    if (i < N_NODES_C * NH) g_x[i] += g_agg[i];
}

// ---------------- head: sigmoid(x @ We + be) ----------------------------------------
__global__ void k_head(const float* __restrict__ We, const float* __restrict__ be,
                       float* __restrict__ out) {
    int n = blockIdx.x * 8 + (threadIdx.x >> 5);
    if (n >= N_NODES_C) return;
    int lane = threadIdx.x & 31;
    const float* xr = g_x + (size_t)n * NH;
    float p0 = 0.f, p1 = 0.f;
#pragma unroll
    for (int u = 0; u < 4; u++) {
        int k = lane + 32 * u;
        float v = xr[k];
        p0 = fmaf(v, We[k * 2 + 0], p0);
        p1 = fmaf(v, We[k * 2 + 1], p1);
    }
#pragma unroll
    for (int o = 16; o; o >>= 1) {
        p0 += __shfl_xor_sync(0xffffffffu, p0, o);
        p1 += __shfl_xor_sync(0xffffffffu, p1, o);
    }
    if (lane == 0) {
        out[(size_t)n * 2 + 0] = sigmoid_f(p0 + be[0]);
        out[(size_t)n * 2 + 1] = sigmoid_f(p1 + be[1]);
    }
}

// ---------------- launch ------------------------------------------------------------
extern "C" void kernel_launch(void* const* d_in, const int* in_sizes, int n_in,
                              void* d_out, int out_size) {
    (void)in_sizes; (void)n_in; (void)out_size;
    const float* x     = (const float*)d_in[0];
    const int*   ei    = (const int*)d_in[1];
    const float* ea    = (const float*)d_in[2];
    const float* W1    = (const float*)d_in[3];
    const float* gamma = (const float*)d_in[4];
    const float* beta  = (const float*)d_in[5];
    const float* W2    = (const float*)d_in[6];
    const float* b2    = (const float*)d_in[7];
    const float* Wa    = (const float*)d_in[8];
    const float* ba    = (const float*)d_in[9];
    const float* Wb    = (const float*)d_in[10];
    const float* Wm    = (const float*)d_in[11];
    const float* bm    = (const float*)d_in[12];
    const float* We    = (const float*)d_in[13];
    const float* be    = (const float*)d_in[14];
    float* out = (float*)d_out;

    void *px = nullptr, *pagg = nullptr, *pstats = nullptr;
    cudaGetSymbolAddress(&px, g_x);
    cudaGetSymbolAddress(&pagg, g_agg);
    cudaGetSymbolAddress(&pstats, g_stats);

    cudaMemcpyAsync(px, x, sizeof(float) * N_NODES_C * NH, cudaMemcpyDeviceToDevice, 0);

    for (int l = 0; l < NLAYERS; l++) {
        k_prep<<<N_EDGES_C / 8, 256>>>(ei);
        cudaMemsetAsync(pstats, 0, 2 * NH * sizeof(float), 0);
        cudaMemsetAsync(pagg, 0, (size_t)N_NODES_C * NH * sizeof(float), 0);
        k_gemm1<<<N_EDGES_C / 32, 128>>>(ei, ea, W1 + (size_t)l * DIN * NH);
        k_stats<<<N_EDGES_C / 512, 128>>>();
        k_bnfin<<<1, 128>>>(gamma + l * NH, beta + l * NH);
        k_fused<<<N_EDGES_C / 32, 128>>>(ei,
                                         W2 + (size_t)l * NH * NH, b2 + l * NH,
                                         Wa + (size_t)l * NH * NH, ba + l * NH,
                                         Wb + l * NH,
                                         Wm + l * NH, bm + l);
        k_apply<<<(N_NODES_C * NH + 255) / 256, 256>>>();
    }
    k_head<<<(N_NODES_C + 7) / 8, 256>>>(We, be, out);
}